// round 2
// baseline (speedup 1.0000x reference)
#include <cuda_runtime.h>
#include <cuda_bf16.h>

#define BB 64
#define LL 200
#define DD 256
#define HH 512
#define G3 1536
#define NQv 1024
#define QQ 1024
#define BH (BB*HH)

#define KP 516   // w_s k-stride (floats)
#define HP 514   // h_s k-stride (floats)

// ------------- device scratch (static, allocation-free) -------------
__device__ float    g_hall[(LL+1)*BH];   // h states, slice t in [0,200]
__device__ float    g_T1[QQ*G3];
__device__ float    g_T2[QQ*G3];
__device__ float    g_A [2*G3];
__device__ float    g_Ad[2*G3];
__device__ float    g_M2[QQ*HH];
__device__ float    g_mb[QQ];
__device__ float    g_mval[BB*LL];
__device__ float    g_pred[BB*LL];
__device__ unsigned g_bar[4];

// ------------- accurate exp / sigmoid / tanh (fast-math-proof) -------------
__device__ __forceinline__ float exp_acc(float x) {
    x = fminf(fmaxf(x, -87.0f), 88.0f);
    float n = rintf(x * 1.4426950408889634f);
    float r = fmaf(-n, 0.693359375f, x);
    r = fmaf(n, 2.12194440e-4f, r);
    float p;
    p = fmaf(r, 1.9841270e-4f, 1.3888889e-3f);
    p = fmaf(r, p, 8.3333338e-3f);
    p = fmaf(r, p, 4.1666668e-2f);
    p = fmaf(r, p, 0.16666667f);
    p = fmaf(r, p, 0.5f);
    p = fmaf(r, p, 1.0f);
    p = fmaf(r, p, 1.0f);
    int e = (int)n;
    return p * __int_as_float((e + 127) << 23);
}
__device__ __forceinline__ float sig_acc(float x)  { return 1.0f / (1.0f + exp_acc(-x)); }
__device__ __forceinline__ float tanh_acc(float x) {
    float e = exp_acc(-2.0f * x);
    return (1.0f - e) / (1.0f + e);
}

// ------------- init: zero h0 slice + barrier counters -------------
__global__ void k_init() {
    int i = blockIdx.x * blockDim.x + threadIdx.x;
    for (int k = i; k < BH; k += gridDim.x * blockDim.x) g_hall[k] = 0.0f;
    if (blockIdx.x == 0 && threadIdx.x < 4) g_bar[threadIdx.x] = 0u;
}

// ------------- fp32 tiled GEMM for precompute -------------
// mode 0: g_T1[m][n] = sum_k q_emb[m+1][k] * (w_ih[n][k] + w_ih[n][256+k]),  K=256, N=1536
// mode 1: g_T2[m][n] = sum_k q_emb_diff[m+1][k] * w_ih[n][256+k],            K=256, N=1536
// mode 2: g_M2[m][n] = sum_k matrix[m][k] * fc_w[k][n],                      K=1024, N=512
__global__ void k_gemm(const float* __restrict__ A, const float* __restrict__ Bsrc,
                       int N, int K, int mode) {
    __shared__ float As[16 * 65];
    __shared__ float Bs[16 * 68];
    float* C = (mode == 0) ? g_T1 : (mode == 1) ? g_T2 : g_M2;
    int tid = threadIdx.x;             // 256 threads
    int tx = tid & 15, ty = tid >> 4;  // tx: n (4 ea), ty: m (4 ea)
    int m0 = blockIdx.y * 64, n0 = blockIdx.x * 64;
    float acc[4][4];
#pragma unroll
    for (int i = 0; i < 4; i++)
#pragma unroll
        for (int j = 0; j < 4; j++) acc[i][j] = 0.0f;

    for (int kt = 0; kt < K; kt += 16) {
        for (int i = tid; i < 1024; i += 256) {
            int m = i >> 4, kk = i & 15;
            int k = kt + kk;
            float v;
            if (mode == 2) v = A[(size_t)(m0 + m) * 1024 + k];
            else           v = A[(size_t)(m0 + m + 1) * 256 + k];
            As[kk * 65 + m] = v;
        }
        for (int i = tid; i < 1024; i += 256) {
            if (mode == 2) {
                int kk = i >> 6, n = i & 63;
                Bs[kk * 68 + n] = Bsrc[(size_t)(kt + kk) * 512 + n0 + n];
            } else {
                int n = i >> 4, kk = i & 15;
                int k = kt + kk;
                float v = Bsrc[(size_t)(n0 + n) * 512 + 256 + k];
                if (mode == 0) v += Bsrc[(size_t)(n0 + n) * 512 + k];
                Bs[kk * 68 + n] = v;
            }
        }
        __syncthreads();
#pragma unroll
        for (int kk = 0; kk < 16; kk++) {
            float a0 = As[kk * 65 + ty * 4 + 0];
            float a1 = As[kk * 65 + ty * 4 + 1];
            float a2 = As[kk * 65 + ty * 4 + 2];
            float a3 = As[kk * 65 + ty * 4 + 3];
            float4 b4 = *(const float4*)&Bs[kk * 68 + tx * 4];
            float av[4] = {a0, a1, a2, a3};
            float bv[4] = {b4.x, b4.y, b4.z, b4.w};
#pragma unroll
            for (int i = 0; i < 4; i++)
#pragma unroll
                for (int j = 0; j < 4; j++) acc[i][j] = fmaf(av[i], bv[j], acc[i][j]);
        }
        __syncthreads();
    }
#pragma unroll
    for (int i = 0; i < 4; i++)
#pragma unroll
        for (int j = 0; j < 4; j++)
            C[(size_t)(m0 + ty * 4 + i) * N + n0 + tx * 4 + j] = acc[i][j];
}

// ------------- small precompute: A, Ad tables, mb vector -------------
__global__ void k_misc(const float* __restrict__ qa_emb, const float* __restrict__ qa_emb_diff,
                       const float* __restrict__ w_ih, const float* __restrict__ matrix,
                       const float* __restrict__ fc_b) {
    int warp = (blockIdx.x * blockDim.x + threadIdx.x) >> 5;
    int lane = threadIdx.x & 31;
    if (warp >= 7168) return;
    float s = 0.0f;
    if (warp < 3072) {
        int a = warp / 1536, n = warp % 1536;
        for (int d = lane; d < 256; d += 32)
            s = fmaf(qa_emb[a * 256 + d], w_ih[(size_t)n * 512 + d], s);
#pragma unroll
        for (int o = 16; o; o >>= 1) s += __shfl_xor_sync(0xffffffffu, s, o);
        if (lane == 0) g_A[a * 1536 + n] = s;
    } else if (warp < 6144) {
        int w = warp - 3072;
        int a = w / 1536, n = w % 1536;
        for (int d = lane; d < 256; d += 32)
            s = fmaf(qa_emb_diff[a * 256 + d], w_ih[(size_t)n * 512 + d], s);
#pragma unroll
        for (int o = 16; o; o >>= 1) s += __shfl_xor_sync(0xffffffffu, s, o);
        if (lane == 0) g_Ad[a * 1536 + n] = s;
    } else {
        int k = warp - 6144;
        for (int q = lane; q < 1024; q += 32)
            s = fmaf(matrix[(size_t)k * 1024 + q], fc_b[q], s);
#pragma unroll
        for (int o = 16; o; o >>= 1) s += __shfl_xor_sync(0xffffffffu, s, o);
        if (lane == 0) g_mb[k] = s;
    }
}

// ------------- persistent GRU recurrence -------------
// grid = 128 blocks: bg = blk>>5 (16 batches each), jg = blk&31 (16 hidden units each).
// 256 threads: bi = tid&15 (batch), ji = tid>>4 (j).
__global__ void __launch_bounds__(256, 1)
k_recur(const int* __restrict__ q_data, const int* __restrict__ qa_data,
        const int* __restrict__ pid_data, const float* __restrict__ diff_parm,
        const float* __restrict__ b_ih, const float* __restrict__ b_hh,
        const float* __restrict__ w_hh) {
    extern __shared__ float sm[];
    float* w_s = sm;                 // 3*16*KP floats
    float* h_s = sm + 3 * 16 * KP;   // 16*HP floats
    int tid = threadIdx.x;
    int bi = tid & 15, ji = tid >> 4;
    int jg = blockIdx.x & 31, bg = blockIdx.x >> 5;
    int b = bg * 16 + bi;
    int j = jg * 16 + ji;

    // stage w_hh slice: gate rows g*512 + (jg*16 + jl)
    for (int i = tid; i < 3 * 16 * 128; i += 256) {
        int row = i >> 7;   // 0..47 = g*16 + jl
        int kc = i & 127;
        int g = row >> 4, jl = row & 15;
        float4 v = *(const float4*)&w_hh[(size_t)(g * 512 + jg * 16 + jl) * 512 + kc * 4];
        *(float4*)&w_s[row * KP + kc * 4] = v;
    }
    const float* wr = &w_s[(0 * 16 + ji) * KP];
    const float* wz = &w_s[(1 * 16 + ji) * KP];
    const float* wn = &w_s[(2 * 16 + ji) * KP];
    float bhr = b_hh[j], bhz = b_hh[512 + j], bhn = b_hh[1024 + j];
    float bir = b_ih[j], biz = b_ih[512 + j], bin_ = b_ih[1024 + j];
    __syncthreads();

    for (int t = 0; t < LL; t++) {
        if (t > 0) {
            if (tid == 0) {
                while (*(volatile unsigned*)&g_bar[bg] < 32u * (unsigned)t) { }
            }
            __syncthreads();
        }
        // stage h[t] for my 16 batches (L2-only loads: peers wrote via L2)
        {
            const float* hsrc = &g_hall[(size_t)t * BH + (size_t)bg * 16 * 512];
            for (int i = tid; i < 16 * 256; i += 256) {
                int bb = i >> 8, kc = i & 255;
                float2 v = __ldcg((const float2*)&hsrc[bb * 512 + kc * 2]);
                *(float2*)&h_s[bb * HP + kc * 2] = v;
            }
        }
        __syncthreads();

        // xg on the fly
        int off = b * LL + t;
        int q = q_data[off];
        int a = (qa_data[off] - q) >> 10;
        float pid = diff_parm[pid_data[off]];
        size_t tb = (size_t)(q - 1) * G3;
        float xr = g_T1[tb + j]        + pid * g_T2[tb + j]        + g_A[a * G3 + j]        + pid * g_Ad[a * G3 + j]        + bir;
        float xz = g_T1[tb + 512 + j]  + pid * g_T2[tb + 512 + j]  + g_A[a * G3 + 512 + j]  + pid * g_Ad[a * G3 + 512 + j]  + biz;
        float xn = g_T1[tb + 1024 + j] + pid * g_T2[tb + 1024 + j] + g_A[a * G3 + 1024 + j] + pid * g_Ad[a * G3 + 1024 + j] + bin_;

        const float* hrow = &h_s[bi * HP];
        float ar0 = 0, ar1 = 0, az0 = 0, az1 = 0, an0 = 0, an1 = 0;
#pragma unroll 4
        for (int k = 0; k < 512; k += 4) {
            float4 w4r = *(const float4*)(wr + k);
            float4 w4z = *(const float4*)(wz + k);
            float4 w4n = *(const float4*)(wn + k);
            float2 hA = *(const float2*)(hrow + k);
            float2 hB = *(const float2*)(hrow + k + 2);
            ar0 = fmaf(hA.x, w4r.x, ar0); ar1 = fmaf(hA.y, w4r.y, ar1);
            ar0 = fmaf(hB.x, w4r.z, ar0); ar1 = fmaf(hB.y, w4r.w, ar1);
            az0 = fmaf(hA.x, w4z.x, az0); az1 = fmaf(hA.y, w4z.y, az1);
            az0 = fmaf(hB.x, w4z.z, az0); az1 = fmaf(hB.y, w4z.w, az1);
            an0 = fmaf(hA.x, w4n.x, an0); an1 = fmaf(hA.y, w4n.y, an1);
            an0 = fmaf(hB.x, w4n.z, an0); an1 = fmaf(hB.y, w4n.w, an1);
        }
        float hr = ar0 + ar1 + bhr;
        float hz = az0 + az1 + bhz;
        float hn = an0 + an1 + bhn;
        float r  = sig_acc(xr + hr);
        float z  = sig_acc(xz + hz);
        float nn = tanh_acc(xn + r * hn);
        float hold = hrow[j];
        float hnew = (1.0f - z) * nn + z * hold;
        __stcg(&g_hall[(size_t)(t + 1) * BH + (size_t)b * 512 + j], hnew);
        __threadfence();
        __syncthreads();
        if (tid == 0) atomicAdd(&g_bar[bg], 1u);
    }
}

// ------------- mvals: got at the asked question, thresholded -------------
__global__ void k_mval(const int* __restrict__ q_data) {
    int w = (blockIdx.x * blockDim.x + threadIdx.x) >> 5;
    int lane = threadIdx.x & 31;
    if (w >= BB * LL) return;
    int b = w / LL, t = w % LL;
    int q = q_data[b * LL + t] - 1;
    const float* m2 = &g_M2[(size_t)q * HH];
    const float* h  = &g_hall[(size_t)(t + 1) * BH + (size_t)b * HH];
    float s = 0.0f;
#pragma unroll
    for (int k = lane; k < HH; k += 32) s = fmaf(m2[k], h[k], s);
#pragma unroll
    for (int o = 16; o; o >>= 1) s += __shfl_xor_sync(0xffffffffu, s, o);
    if (lane == 0) {
        float got = s + g_mb[q];
        g_mval[b * LL + t] = (got >= 0.4f) ? 1.0f : got;
    }
}

// ------------- stats + DINA scan (8 blocks x 8 batches, state in smem) -------------
__global__ void k_scan(const int* __restrict__ q_data, const int* __restrict__ qa_data) {
    extern __shared__ float sms[];
    float* guess = sms;                  // 8*1024
    float* slip  = sms + 8192;           // 8*1024
    float* s_mv  = sms + 16384;          // 8*200 each below
    float* s_mc  = s_mv + 1600;
    float* s_mi  = s_mc + 1600;
    float* s_nmc = s_mi + 1600;
    float* s_aa  = s_nmc + 1600;
    int*   s_q   = (int*)(s_aa + 1600);
    int*   s_qa  = s_q + 1600;

    int tid = threadIdx.x;
    int b0 = blockIdx.x * 8;
    for (int i = tid; i < 16384; i += 256) { guess[i] = 0.0f; slip[i] = 0.0f; }
    for (int i = tid; i < 1600; i += 256) {
        int lb = i / 200, t = i % 200;
        int off = (b0 + lb) * 200 + t;
        int q = q_data[off];
        s_q[i]  = q;
        s_qa[i] = (qa_data[off] - q) >> 10;
        s_mv[i] = g_mval[off];
    }
    __syncthreads();
    for (int i = tid; i < 1600; i += 256) {
        int lb = i / 200, t = i % 200;
        int base = lb * 200;
        int qt = s_q[base + t];
        int aa = 0; float mc = 0, mi = 0, nmc = 0;
        for (int k = 0; k <= t; k++) {
            if (s_q[base + k] == qt) {
                aa++;
                if (k < t) {
                    float m = s_mv[base + k];
                    bool ma = (m == 1.0f), nm = (m == 0.0f);
                    if (s_qa[base + k] == 1) { if (ma) mc += 1.0f; }
                    else { if (ma) mi += 1.0f; if (nm) nmc += 1.0f; }
                }
            }
        }
        s_mc[i] = mc; s_mi[i] = mi; s_nmc[i] = nmc; s_aa[i] = (float)aa;
    }
    __syncthreads();
    if (tid < 8) {
        int lb = tid;
        float* G = guess + lb * 1024;
        float* S = slip  + lb * 1024;
        for (int t = 0; t < 200; t++) {
            int ii = lb * 200 + t;
            int iq = s_q[ii] - 1;
            float m = s_mv[ii];
            int qa = s_qa[ii];
            float aav = s_aa[ii];
            float g_upd = (m == 1.0f) ? __fdiv_rn(s_mc[ii], aav)
                          : ((qa == 0) ? (1.0f - __fdiv_rn(s_nmc[ii], aav))
                                       : __fdiv_rn(s_nmc[ii], aav));
            bool upd = (m == 1.0f) && (qa == 0);
            float gi = G[iq], si = S[iq];
            float ng = upd ? gi : g_upd;
            float ns = upd ? __fdiv_rn(s_mi[ii], aav) : si;
            G[iq] = ng; S[iq] = ns;
            float p = (1.0f - ns) * (m * ng + (1.0f - ns) * (1.0f - m));
            g_pred[(b0 + lb) * 200 + t] = p;
        }
    }
}

// ------------- loss + sigmoid + count -------------
__global__ void k_final(const float* __restrict__ target, const int* __restrict__ pid_data,
                        const float* __restrict__ diff_parm, float* __restrict__ out,
                        int out_size) {
    __shared__ double red[256];
    __shared__ double red2[256];
    __shared__ int redc[256];
    int tid = threadIdx.x;
    double mse = 0.0, creg = 0.0; int cnt = 0;
    int poff = (out_size == BB * LL + 2) ? 1 : 0;
    for (int i = tid; i < BB * LL; i += 256) {
        float p = g_pred[i];
        float lab = target[i];
        if (lab > -0.9f) { float d = p - lab; mse += (double)(d * d); cnt++; }
        float pd = diff_parm[pid_data[i]];
        creg += (double)(pd * pd);
        if (poff + i < out_size) out[poff + i] = sig_acc(p);
    }
    red[tid] = mse; red2[tid] = creg; redc[tid] = cnt;
    __syncthreads();
    for (int s = 128; s; s >>= 1) {
        if (tid < s) { red[tid] += red[tid + s]; red2[tid] += red2[tid + s]; redc[tid] += redc[tid + s]; }
        __syncthreads();
    }
    if (tid == 0 && out_size == BB * LL + 2) {
        out[0] = (float)(red[0] + red2[0] * 1e-5);
        out[BB * LL + 1] = (float)redc[0];
    }
}

extern "C" void kernel_launch(void* const* d_in, const int* in_sizes, int n_in,
                              void* d_out, int out_size) {
    const int*   q_data      = (const int*)d_in[0];
    const int*   qa_data     = (const int*)d_in[1];
    const int*   pid_data    = (const int*)d_in[2];
    const float* matrix      = (const float*)d_in[3];
    const float* target      = (const float*)d_in[4];
    const float* q_emb       = (const float*)d_in[5];
    const float* qa_emb      = (const float*)d_in[6];
    const float* q_emb_diff  = (const float*)d_in[7];
    const float* qa_emb_diff = (const float*)d_in[8];
    const float* diff_parm   = (const float*)d_in[9];
    const float* w_ih        = (const float*)d_in[10];
    const float* w_hh        = (const float*)d_in[11];
    const float* b_ih        = (const float*)d_in[12];
    const float* b_hh        = (const float*)d_in[13];
    const float* fc_w        = (const float*)d_in[14];
    const float* fc_b        = (const float*)d_in[15];
    float* out = (float*)d_out;

    int recur_smem = (3 * 16 * KP + 16 * HP) * 4;                // 131968 B
    int scan_smem  = (16384 + 5 * 1600) * 4 + 2 * 1600 * 4;      // 110336 B
    cudaFuncSetAttribute(k_recur, cudaFuncAttributeMaxDynamicSharedMemorySize, recur_smem);
    cudaFuncSetAttribute(k_scan,  cudaFuncAttributeMaxDynamicSharedMemorySize, scan_smem);

    k_init<<<64, 256>>>();
    k_gemm<<<dim3(24, 16), 256>>>(q_emb,      w_ih, 1536, 256, 0);   // T1
    k_gemm<<<dim3(24, 16), 256>>>(q_emb_diff, w_ih, 1536, 256, 1);   // T2
    k_gemm<<<dim3(8, 16),  256>>>(matrix,     fc_w, 512, 1024, 2);   // M2
    k_misc<<<896, 256>>>(qa_emb, qa_emb_diff, w_ih, matrix, fc_b);
    k_recur<<<128, 256, recur_smem>>>(q_data, qa_data, pid_data, diff_parm,
                                      b_ih, b_hh, w_hh);
    k_mval<<<1600, 256>>>(q_data);
    k_scan<<<8, 256, scan_smem>>>(q_data, qa_data);
    k_final<<<1, 256>>>(target, pid_data, diff_parm, out, out_size);
}

// round 6
// speedup vs baseline: 1.2964x; 1.2964x over previous
#include <cuda_runtime.h>
#include <cuda_bf16.h>

#define BB 64
#define LL 200
#define DD 256
#define HH 512
#define G3 1536
#define QQ 1024
#define BH (BB*HH)

#define KP 516   // w_s k-stride (floats)
#define HP 516   // h_s k-stride (floats)

// ------------- device scratch (static, allocation-free) -------------
__device__ float    g_hall[(LL+1)*BH];
__device__ float    g_T1[QQ*G3];
__device__ float    g_T2[QQ*G3];
__device__ float    g_A [2*G3];
__device__ float    g_Ad[2*G3];
__device__ float    g_M2[QQ*HH];
__device__ float    g_mb[QQ];
__device__ float    g_mval[BB*LL];
__device__ float    g_pred[BB*LL];
__device__ unsigned g_bar[4];

// ------------- f32x2 packed helpers -------------
__device__ __forceinline__ unsigned long long ffma2(unsigned long long a, unsigned long long b,
                                                    unsigned long long c) {
    unsigned long long d;
    asm("fma.rn.f32x2 %0, %1, %2, %3;" : "=l"(d) : "l"(a), "l"(b), "l"(c));
    return d;
}
__device__ __forceinline__ unsigned long long dup2(float a) {
    unsigned long long d; asm("mov.b64 %0, {%1, %1};" : "=l"(d) : "f"(a)); return d;
}
__device__ __forceinline__ unsigned long long pack2(float x, float y) {
    unsigned long long d; asm("mov.b64 %0, {%1, %2};" : "=l"(d) : "f"(x), "f"(y)); return d;
}
__device__ __forceinline__ float2 unpack2(unsigned long long v) {
    float2 r; asm("mov.b64 {%0, %1}, %2;" : "=f"(r.x), "=f"(r.y) : "l"(v)); return r;
}
__device__ __forceinline__ void red_release(unsigned* p) {
    asm volatile("red.release.gpu.add.u32 [%0], 1;" :: "l"(p) : "memory");
}
__device__ __forceinline__ unsigned ld_acquire(unsigned* p) {
    unsigned v; asm volatile("ld.acquire.gpu.u32 %0, [%1];" : "=r"(v) : "l"(p) : "memory");
    return v;
}
__device__ __forceinline__ float fsel(float2 v, int jj) { return jj ? v.y : v.x; }

// ------------- accurate exp / sigmoid / tanh (fast-math-proof) -------------
__device__ __forceinline__ float exp_acc(float x) {
    x = fminf(fmaxf(x, -87.0f), 88.0f);
    float n = rintf(x * 1.4426950408889634f);
    float r = fmaf(-n, 0.693359375f, x);
    r = fmaf(n, 2.12194440e-4f, r);
    float p;
    p = fmaf(r, 1.9841270e-4f, 1.3888889e-3f);
    p = fmaf(r, p, 8.3333338e-3f);
    p = fmaf(r, p, 4.1666668e-2f);
    p = fmaf(r, p, 0.16666667f);
    p = fmaf(r, p, 0.5f);
    p = fmaf(r, p, 1.0f);
    p = fmaf(r, p, 1.0f);
    int e = (int)n;
    return p * __int_as_float((e + 127) << 23);
}
__device__ __forceinline__ float sig_acc(float x)  { return 1.0f / (1.0f + exp_acc(-x)); }
__device__ __forceinline__ float tanh_acc(float x) {
    float e = exp_acc(-2.0f * x);
    return (1.0f - e) / (1.0f + e);
}

// ------------- merged precompute: 3 GEMMs + small tables + init -------------
// blocks [0,384): T1   [384,768): T2   [768,896): M2
// blocks [896,1792): misc tables (A, Ad, mb)
// blocks [1792,1856): zero h0 slice + barrier counters
__global__ void __launch_bounds__(256) k_pre(
        const float* __restrict__ q_emb, const float* __restrict__ q_emb_diff,
        const float* __restrict__ matrix, const float* __restrict__ fc_w,
        const float* __restrict__ w_ih, const float* __restrict__ qa_emb,
        const float* __restrict__ qa_emb_diff, const float* __restrict__ fc_b) {
    __shared__ float As[16 * 65];
    __shared__ float Bs[16 * 68];
    int blk = blockIdx.x;
    int tid = threadIdx.x;

    if (blk < 896) {
        const float* A; const float* Bsrc; float* C; int N, K, mode, bx, by;
        if (blk < 384)      { mode = 0; A = q_emb;      Bsrc = w_ih; C = g_T1; N = 1536; K = 256;  bx = blk % 24;  by = blk / 24; }
        else if (blk < 768) { int r = blk - 384; mode = 1; A = q_emb_diff; Bsrc = w_ih; C = g_T2; N = 1536; K = 256; bx = r % 24; by = r / 24; }
        else                { int r = blk - 768; mode = 2; A = matrix;     Bsrc = fc_w; C = g_M2; N = 512;  K = 1024; bx = r % 8; by = r / 8; }
        int tx = tid & 15, ty = tid >> 4;
        int m0 = by * 64, n0 = bx * 64;
        unsigned long long acc2[4][2];
#pragma unroll
        for (int i = 0; i < 4; i++) { acc2[i][0] = 0ull; acc2[i][1] = 0ull; }

        for (int kt = 0; kt < K; kt += 16) {
            for (int i = tid; i < 1024; i += 256) {
                int m = i >> 4, kk = i & 15;
                int k = kt + kk;
                float v;
                if (mode == 2) v = A[(size_t)(m0 + m) * 1024 + k];
                else           v = A[(size_t)(m0 + m + 1) * 256 + k];
                As[kk * 65 + m] = v;
            }
            for (int i = tid; i < 1024; i += 256) {
                if (mode == 2) {
                    int kk = i >> 6, n = i & 63;
                    Bs[kk * 68 + n] = Bsrc[(size_t)(kt + kk) * 512 + n0 + n];
                } else {
                    int n = i >> 4, kk = i & 15;
                    int k = kt + kk;
                    float v = Bsrc[(size_t)(n0 + n) * 512 + 256 + k];
                    if (mode == 0) v += Bsrc[(size_t)(n0 + n) * 512 + k];
                    Bs[kk * 68 + n] = v;
                }
            }
            __syncthreads();
#pragma unroll
            for (int kk = 0; kk < 16; kk++) {
                float4 b4 = *(const float4*)&Bs[kk * 68 + tx * 4];
                unsigned long long b01 = pack2(b4.x, b4.y);
                unsigned long long b23 = pack2(b4.z, b4.w);
#pragma unroll
                for (int i = 0; i < 4; i++) {
                    unsigned long long da = dup2(As[kk * 65 + ty * 4 + i]);
                    acc2[i][0] = ffma2(da, b01, acc2[i][0]);
                    acc2[i][1] = ffma2(da, b23, acc2[i][1]);
                }
            }
            __syncthreads();
        }
#pragma unroll
        for (int i = 0; i < 4; i++) {
            float2 c01 = unpack2(acc2[i][0]);
            float2 c23 = unpack2(acc2[i][1]);
            float4 o = make_float4(c01.x, c01.y, c23.x, c23.y);
            *(float4*)&C[(size_t)(m0 + ty * 4 + i) * N + n0 + tx * 4] = o;
        }
    } else if (blk < 1792) {
        int warp = (blk - 896) * 8 + (tid >> 5);
        int lane = tid & 31;
        float s = 0.0f;
        if (warp < 3072) {
            int a = warp / 1536, n = warp % 1536;
            for (int d = lane; d < 256; d += 32)
                s = fmaf(qa_emb[a * 256 + d], w_ih[(size_t)n * 512 + d], s);
#pragma unroll
            for (int o = 16; o; o >>= 1) s += __shfl_xor_sync(0xffffffffu, s, o);
            if (lane == 0) g_A[a * 1536 + n] = s;
        } else if (warp < 6144) {
            int w = warp - 3072;
            int a = w / 1536, n = w % 1536;
            for (int d = lane; d < 256; d += 32)
                s = fmaf(qa_emb_diff[a * 256 + d], w_ih[(size_t)n * 512 + d], s);
#pragma unroll
            for (int o = 16; o; o >>= 1) s += __shfl_xor_sync(0xffffffffu, s, o);
            if (lane == 0) g_Ad[a * 1536 + n] = s;
        } else {
            int k = warp - 6144;
            for (int q = lane; q < 1024; q += 32)
                s = fmaf(matrix[(size_t)k * 1024 + q], fc_b[q], s);
#pragma unroll
            for (int o = 16; o; o >>= 1) s += __shfl_xor_sync(0xffffffffu, s, o);
            if (lane == 0) g_mb[k] = s;
        }
    } else {
        int r = blk - 1792;
        for (int k = r * 256 + tid; k < BH; k += 64 * 256) g_hall[k] = 0.0f;
        if (r == 0 && tid < 4) g_bar[tid] = 0u;
    }
}

// ------------- persistent GRU recurrence -------------
// 128 blocks: bg = blk>>5 (16 batches), jg = blk&31 (16 hidden j).
// 256 threads: lane: bi = lane&15, half = lane>>4 (k-split); warp jp: j-pair {2jp, 2jp+1}.
__global__ void __launch_bounds__(256, 1)
k_recur(const int* __restrict__ q_data, const int* __restrict__ qa_data,
        const int* __restrict__ pid_data, const float* __restrict__ diff_parm,
        const float* __restrict__ b_ih, const float* __restrict__ b_hh,
        const float* __restrict__ w_hh) {
    extern __shared__ float sm[];
    float* w_s = sm;                 // 48 rows * KP
    float* h_s = sm + 48 * KP;       // 16 rows * HP
    int tid  = threadIdx.x;
    int lane = tid & 31;
    int bi   = lane & 15;
    int half = lane >> 4;
    int jp   = tid >> 5;             // 0..7
    int jg = blockIdx.x & 31, bg = blockIdx.x >> 5;
    int b   = bg * 16 + bi;
    int j0g = jg * 16 + jp * 2;

    // stage w_hh slice
    for (int i = tid; i < 48 * 128; i += 256) {
        int row = i >> 7, kc = i & 127;
        int g = row >> 4, jl = row & 15;
        float4 v = *(const float4*)&w_hh[(size_t)(g * 512 + jg * 16 + jl) * 512 + kc * 4];
        *(float4*)&w_s[row * KP + kc * 4] = v;
    }
    const float* wp[3][2];
#pragma unroll
    for (int g = 0; g < 3; g++)
#pragma unroll
        for (int jj = 0; jj < 2; jj++)
            wp[g][jj] = w_s + (g * 16 + jp * 2 + jj) * KP + half * 256;

    float2 bih2[3], bhh2[3];
#pragma unroll
    for (int g = 0; g < 3; g++) {
        bih2[g] = *(const float2*)&b_ih[g * 512 + j0g];
        bhh2[g] = *(const float2*)&b_hh[g * 512 + j0g];
    }
    __syncthreads();

    for (int t = 0; t < LL; t++) {
        // prefetch xg pieces (independent of h -> overlaps the spin wait)
        int off = b * LL + t;
        int q = q_data[off];
        int a = (qa_data[off] - q) >> 10;
        float pid = diff_parm[pid_data[off]];
        size_t tb = (size_t)(q - 1) * G3 + j0g;
        size_t ab = (size_t)a * G3 + j0g;
        float2 t1v[3], t2v[3], av[3], adv[3];
#pragma unroll
        for (int g = 0; g < 3; g++) {
            t1v[g] = *(const float2*)&g_T1[tb + g * 512];
            t2v[g] = *(const float2*)&g_T2[tb + g * 512];
            av[g]  = *(const float2*)&g_A [ab + g * 512];
            adv[g] = *(const float2*)&g_Ad[ab + g * 512];
        }

        if (t > 0) {
            if (tid == 0) {
                while (ld_acquire(&g_bar[bg]) < 32u * (unsigned)t) { }
            }
            __syncthreads();
        }
        // stage h[t] for my 16 batches
        {
            const float* hsrc = &g_hall[(size_t)t * BH + (size_t)bg * 16 * 512];
            for (int i = tid; i < 2048; i += 256) {
                int bb = i >> 7, kc = i & 127;
                float4 v = __ldcg((const float4*)&hsrc[bb * 512 + kc * 4]);
                *(float4*)&h_s[bb * HP + kc * 4] = v;
            }
        }
        __syncthreads();

        const float* hrow = h_s + bi * HP + half * 256;
        unsigned long long accA[3][2], accB[3][2];
#pragma unroll
        for (int g = 0; g < 3; g++) {
            accA[g][0] = accA[g][1] = 0ull;
            accB[g][0] = accB[g][1] = 0ull;
        }
#pragma unroll 2
        for (int k = 0; k < 256; k += 8) {
            ulonglong2 hA = *(const ulonglong2*)(hrow + k);
            ulonglong2 hB = *(const ulonglong2*)(hrow + k + 4);
#pragma unroll
            for (int g = 0; g < 3; g++)
#pragma unroll
                for (int jj = 0; jj < 2; jj++) {
                    ulonglong2 wA = *(const ulonglong2*)(wp[g][jj] + k);
                    ulonglong2 wB = *(const ulonglong2*)(wp[g][jj] + k + 4);
                    accA[g][jj] = ffma2(hA.x, wA.x, accA[g][jj]);
                    accA[g][jj] = ffma2(hA.y, wA.y, accA[g][jj]);
                    accB[g][jj] = ffma2(hB.x, wB.x, accB[g][jj]);
                    accB[g][jj] = ffma2(hB.y, wB.y, accB[g][jj]);
                }
        }
        float dot[3][2];
#pragma unroll
        for (int g = 0; g < 3; g++)
#pragma unroll
            for (int jj = 0; jj < 2; jj++) {
                float2 pa = unpack2(accA[g][jj]);
                float2 pb = unpack2(accB[g][jj]);
                float s = (pa.x + pa.y) + (pb.x + pb.y);
                s += __shfl_xor_sync(0xffffffffu, s, 16);
                dot[g][jj] = s;
            }

        float2 hold = *(const float2*)(h_s + bi * HP + j0g);
        float out0 = 0.0f, out1 = 0.0f;
#pragma unroll
        for (int jj = 0; jj < 2; jj++) {
            float xr = fsel(t1v[0], jj) + pid * fsel(t2v[0], jj) + fsel(av[0], jj) + pid * fsel(adv[0], jj) + fsel(bih2[0], jj);
            float xz = fsel(t1v[1], jj) + pid * fsel(t2v[1], jj) + fsel(av[1], jj) + pid * fsel(adv[1], jj) + fsel(bih2[1], jj);
            float xn = fsel(t1v[2], jj) + pid * fsel(t2v[2], jj) + fsel(av[2], jj) + pid * fsel(adv[2], jj) + fsel(bih2[2], jj);
            float hr = dot[0][jj] + fsel(bhh2[0], jj);
            float hz = dot[1][jj] + fsel(bhh2[1], jj);
            float hn = dot[2][jj] + fsel(bhh2[2], jj);
            float r  = sig_acc(xr + hr);
            float z  = sig_acc(xz + hz);
            float nn = tanh_acc(xn + r * hn);
            float ho = jj ? hold.y : hold.x;
            float hv = (1.0f - z) * nn + z * ho;
            if (jj) out1 = hv; else out0 = hv;
        }
        if (half == 0) {
            float2 st = make_float2(out0, out1);
            __stcg((float2*)&g_hall[(size_t)(t + 1) * BH + (size_t)b * 512 + j0g], st);
        }
        __syncthreads();
        if (tid == 0) red_release(&g_bar[bg]);
    }
}

// ------------- mvals: got at the asked question, thresholded -------------
__global__ void k_mval(const int* __restrict__ q_data) {
    int w = (blockIdx.x * blockDim.x + threadIdx.x) >> 5;
    int lane = threadIdx.x & 31;
    if (w >= BB * LL) return;
    int b = w / LL, t = w % LL;
    int q = q_data[b * LL + t] - 1;
    const float* m2 = &g_M2[(size_t)q * HH];
    const float* h  = &g_hall[(size_t)(t + 1) * BH + (size_t)b * HH];
    float s = 0.0f;
#pragma unroll
    for (int k = lane; k < HH; k += 32) s = fmaf(m2[k], h[k], s);
#pragma unroll
    for (int o = 16; o; o >>= 1) s += __shfl_xor_sync(0xffffffffu, s, o);
    if (lane == 0) {
        float got = s + g_mb[q];
        g_mval[b * LL + t] = (got >= 0.4f) ? 1.0f : got;
    }
}

// ------------- stats + DINA scan -------------
__global__ void k_scan(const int* __restrict__ q_data, const int* __restrict__ qa_data) {
    extern __shared__ float sms[];
    float* guess = sms;
    float* slip  = sms + 8192;
    float* s_mv  = sms + 16384;
    float* s_mc  = s_mv + 1600;
    float* s_mi  = s_mc + 1600;
    float* s_nmc = s_mi + 1600;
    float* s_aa  = s_nmc + 1600;
    int*   s_q   = (int*)(s_aa + 1600);
    int*   s_qa  = s_q + 1600;

    int tid = threadIdx.x;
    int b0 = blockIdx.x * 8;
    for (int i = tid; i < 16384; i += 256) { guess[i] = 0.0f; slip[i] = 0.0f; }
    for (int i = tid; i < 1600; i += 256) {
        int lb = i / 200, t = i % 200;
        int off = (b0 + lb) * 200 + t;
        int q = q_data[off];
        s_q[i]  = q;
        s_qa[i] = (qa_data[off] - q) >> 10;
        s_mv[i] = g_mval[off];
    }
    __syncthreads();
    for (int i = tid; i < 1600; i += 256) {
        int lb = i / 200, t = i % 200;
        int base = lb * 200;
        int qt = s_q[base + t];
        int aa = 0; float mc = 0, mi = 0, nmc = 0;
        for (int k = 0; k <= t; k++) {
            if (s_q[base + k] == qt) {
                aa++;
                if (k < t) {
                    float m = s_mv[base + k];
                    bool ma = (m == 1.0f), nm = (m == 0.0f);
                    if (s_qa[base + k] == 1) { if (ma) mc += 1.0f; }
                    else { if (ma) mi += 1.0f; if (nm) nmc += 1.0f; }
                }
            }
        }
        s_mc[i] = mc; s_mi[i] = mi; s_nmc[i] = nmc; s_aa[i] = (float)aa;
    }
    __syncthreads();
    if (tid < 8) {
        int lb = tid;
        float* G = guess + lb * 1024;
        float* S = slip  + lb * 1024;
        for (int t = 0; t < 200; t++) {
            int ii = lb * 200 + t;
            int iq = s_q[ii] - 1;
            float m = s_mv[ii];
            int qa = s_qa[ii];
            float aav = s_aa[ii];
            float g_upd = (m == 1.0f) ? __fdiv_rn(s_mc[ii], aav)
                          : ((qa == 0) ? (1.0f - __fdiv_rn(s_nmc[ii], aav))
                                       : __fdiv_rn(s_nmc[ii], aav));
            bool upd = (m == 1.0f) && (qa == 0);
            float gi = G[iq], si = S[iq];
            float ng = upd ? gi : g_upd;
            float ns = upd ? __fdiv_rn(s_mi[ii], aav) : si;
            G[iq] = ng; S[iq] = ns;
            float p = (1.0f - ns) * (m * ng + (1.0f - ns) * (1.0f - m));
            g_pred[(b0 + lb) * 200 + t] = p;
        }
    }
}

// ------------- loss + sigmoid + count -------------
__global__ void k_final(const float* __restrict__ target, const int* __restrict__ pid_data,
                        const float* __restrict__ diff_parm, float* __restrict__ out,
                        int out_size) {
    __shared__ double red[256];
    __shared__ double red2[256];
    __shared__ int redc[256];
    int tid = threadIdx.x;
    double mse = 0.0, creg = 0.0; int cnt = 0;
    int poff = (out_size == BB * LL + 2) ? 1 : 0;
    for (int i = tid; i < BB * LL; i += 256) {
        float p = g_pred[i];
        float lab = target[i];
        if (lab > -0.9f) { float d = p - lab; mse += (double)(d * d); cnt++; }
        float pd = diff_parm[pid_data[i]];
        creg += (double)(pd * pd);
        if (poff + i < out_size) out[poff + i] = sig_acc(p);
    }
    red[tid] = mse; red2[tid] = creg; redc[tid] = cnt;
    __syncthreads();
    for (int s = 128; s; s >>= 1) {
        if (tid < s) { red[tid] += red[tid + s]; red2[tid] += red2[tid + s]; redc[tid] += redc[tid + s]; }
        __syncthreads();
    }
    if (tid == 0 && out_size == BB * LL + 2) {
        out[0] = (float)(red[0] + red2[0] * 1e-5);
        out[BB * LL + 1] = (float)redc[0];
    }
}

extern "C" void kernel_launch(void* const* d_in, const int* in_sizes, int n_in,
                              void* d_out, int out_size) {
    const int*   q_data      = (const int*)d_in[0];
    const int*   qa_data     = (const int*)d_in[1];
    const int*   pid_data    = (const int*)d_in[2];
    const float* matrix      = (const float*)d_in[3];
    const float* target      = (const float*)d_in[4];
    const float* q_emb       = (const float*)d_in[5];
    const float* qa_emb      = (const float*)d_in[6];
    const float* q_emb_diff  = (const float*)d_in[7];
    const float* qa_emb_diff = (const float*)d_in[8];
    const float* diff_parm   = (const float*)d_in[9];
    const float* w_ih        = (const float*)d_in[10];
    const float* w_hh        = (const float*)d_in[11];
    const float* b_ih        = (const float*)d_in[12];
    const float* b_hh        = (const float*)d_in[13];
    const float* fc_w        = (const float*)d_in[14];
    const float* fc_b        = (const float*)d_in[15];
    float* out = (float*)d_out;

    int recur_smem = (48 * KP + 16 * HP) * 4;                    // 132096 B
    int scan_smem  = (16384 + 5 * 1600) * 4 + 2 * 1600 * 4;      // 110336 B
    cudaFuncSetAttribute(k_recur, cudaFuncAttributeMaxDynamicSharedMemorySize, recur_smem);
    cudaFuncSetAttribute(k_scan,  cudaFuncAttributeMaxDynamicSharedMemorySize, scan_smem);

    k_pre<<<1856, 256>>>(q_emb, q_emb_diff, matrix, fc_w, w_ih, qa_emb, qa_emb_diff, fc_b);
    k_recur<<<128, 256, recur_smem>>>(q_data, qa_data, pid_data, diff_parm,
                                      b_ih, b_hh, w_hh);
    k_mval<<<1600, 256>>>(q_data);
    k_scan<<<8, 256, scan_smem>>>(q_data, qa_data);
    k_final<<<1, 256>>>(target, pid_data, diff_parm, out, out_size);
}